// round 14
// baseline (speedup 1.0000x reference)
#include <cuda_runtime.h>
#include <cuda_fp16.h>
#include <cstdint>

// ===========================================================================
// Fused poker-feature MLP via mma.sync (HMMA fp16).
//   out[B,256] = relu(x @ W1 + b1) @ W2 + b2,  x = [hole|board|feats] (119)
//
// R13 = R12 (360.9us; single-sync 3-slot ring) + A2 fragments register-
//       cached across GEMM2's two halves (stage B loads them once inside
//       the ks loop, stage C reuses from regs): -16 LDS.128/warp/chunk
//       (~15% of all smem-crossbar bytes, the binding resource).
// Math identical to R9/R12: GEMM1 = Ah*B + featlo*B ; GEMM2 = Ah*B per half.
// ===========================================================================

#define NT     512
#define BM     128
#define IND    119
#define HID    1024
#define OUTDIM 256

// smem byte offsets
#define A1H_B 0u        // [mb8][ks8][lane32][16B] = 32KB
#define A1L_B 32768u    // [mb8][ks2][lane32][16B] = 8KB (k 96..127 only)
#define A2H_B 40960u    // [mb8][ks8][lane32][16B] = 32KB
#define BB_B  73728u    // 3 x 32KB piece slots
#define SMEMB 172032u

#define NPIECES 24      // 8 chunks x 3 pieces (W1, W2h0, W2h1)

// fragment-ordered weight images (fp16 hi only)
__device__ __align__(16) unsigned char gW1frag[8 * 32768];   // [c]
__device__ __align__(16) unsigned char gW2frag[16 * 32768];  // [c][half]

// ---------------------------------------------------------------------------
__device__ __forceinline__ unsigned pack_f16(float a, float b) {
    __half2 t = __floats2half2_rn(a, b);
    return *(unsigned*)&t;
}
__device__ __forceinline__ float f16rt(float a) {
    return __half2float(__float2half_rn(a));
}
__device__ __forceinline__ uint32_t smem_u32(const void* p) {
    uint32_t a;
    asm("{ .reg .u64 t; cvta.to.shared.u64 t, %1; cvt.u32.u64 %0, t; }"
        : "=r"(a) : "l"(p));
    return a;
}
__device__ __forceinline__ void mma16816(float c[4], const uint4& A,
                                         unsigned b0, unsigned b1) {
    asm volatile(
        "mma.sync.aligned.m16n8k16.row.col.f32.f16.f16.f32 "
        "{%0,%1,%2,%3}, {%4,%5,%6,%7}, {%8,%9}, {%0,%1,%2,%3};\n"
        : "+f"(c[0]), "+f"(c[1]), "+f"(c[2]), "+f"(c[3])
        : "r"(A.x), "r"(A.y), "r"(A.z), "r"(A.w), "r"(b0), "r"(b1));
}
#define CP_WAIT1() asm volatile("cp.async.wait_group 1;" ::: "memory")

// byte offset of element (row r, col cl) in an A-fragment region (8 mblks)
__device__ __forceinline__ uint32_t afrag_off(int r, int cl) {
    int mb = r >> 4, i = r & 15, ks = cl >> 4, jj = cl & 15;
    int lane = ((i & 7) << 2) + ((jj & 7) >> 1);
    int reg = (i >> 3) + ((jj >> 3) << 1);
    return ((((mb << 3) + ks) << 5) + lane) * 16u + (reg << 2) + ((jj & 1) << 1);
}
// 2-kstep lo region (k 96..127)
__device__ __forceinline__ uint32_t lofrag_off(int r, int cl) {
    int mb = r >> 4, i = r & 15, ks = (cl >> 4) - 6, jj = cl & 15;
    int lane = ((i & 7) << 2) + ((jj & 7) >> 1);
    int reg = (i >> 3) + ((jj >> 3) << 1);
    return ((((mb << 1) + ks) << 5) + lane) * 16u + (reg << 2) + ((jj & 1) << 1);
}

// ---------------------------------------------------------------------------
// Prep: cook fp16 fragment images (layout identical to R9).
// ---------------------------------------------------------------------------
__global__ void prep_w1(const float* __restrict__ W1) {
    int id = blockIdx.x * blockDim.x + threadIdx.x;
    if (id >= 8 * 8192) return;
    int c = id >> 13, q = id & 8191;
    int ks = q >> 10, n16 = (q >> 7) & 7, lane = (q >> 2) & 31, j = q & 3;
    int n8 = n16 * 2 + (j >> 1), breg = j & 1;
    int k = ks * 16 + (lane & 3) * 2 + breg * 8;
    int n = n8 * 8 + (lane >> 2);
    float v0 = (k < IND)     ? W1[k * HID + c * 128 + n]       : 0.0f;
    float v1 = (k + 1 < IND) ? W1[(k + 1) * HID + c * 128 + n] : 0.0f;
    ((unsigned*)gW1frag)[c * 8192 + q] = pack_f16(v0, v1);
}
__global__ void prep_w2(const float* __restrict__ W2) {
    int id = blockIdx.x * blockDim.x + threadIdx.x;
    if (id >= 16 * 8192) return;
    int pi = id >> 13, q = id & 8191;
    int c = pi >> 1, half = pi & 1;
    int ks = q >> 10, n16 = (q >> 7) & 7, lane = (q >> 2) & 31, j = q & 3;
    int n8 = n16 * 2 + (j >> 1), breg = j & 1;
    int k = ks * 16 + (lane & 3) * 2 + breg * 8;
    int n = n8 * 8 + (lane >> 2);
    float v0 = W2[(c * 128 + k) * OUTDIM + half * 128 + n];
    float v1 = W2[(c * 128 + k + 1) * OUTDIM + half * 128 + n];
    ((unsigned*)gW2frag)[pi * 8192 + q] = pack_f16(v0, v1);
}

// ---------------------------------------------------------------------------
__device__ __forceinline__ const unsigned char* piece_src(int p) {
    int c = p / 3, t = p % 3;
    if (t == 0) return gW1frag + (size_t)c * 32768u;
    return gW2frag + (size_t)((c << 1) + (t - 1)) * 32768u;
}
// slot for piece p in the 3-slot ring
__device__ __forceinline__ uint32_t piece_slot(int p) {
    return (uint32_t)(p % 3) * 32768u;
}
__device__ __forceinline__ void issue_piece(int p, uint32_t bb_u32, int tid) {
    if (p < NPIECES) {
        const unsigned char* src = piece_src(p) + tid * 64;
        uint32_t dst = bb_u32 + piece_slot(p) + (uint32_t)tid * 64u;
#pragma unroll
        for (int i = 0; i < 4; i++)
            asm volatile("cp.async.cg.shared.global [%0], [%1], 16;"
                         :: "r"(dst + i * 16), "l"(src + i * 16));
    }
    asm volatile("cp.async.commit_group;" ::: "memory");
}

// full-K single-A term with smem A (GEMM1 hi)
__device__ __forceinline__ void gemm_term(float C[2][4][4],
                                          const uint4* __restrict__ aF,
                                          const uint4* __restrict__ sb,
                                          int mb0, int n16a, int lane) {
#pragma unroll
    for (int ks = 0; ks < 8; ks++) {
        uint4 Be = sb[(ks * 8 + n16a) * 32 + lane];
        uint4 Bo = sb[(ks * 8 + n16a + 1) * 32 + lane];
        uint4 A0 = aF[(mb0 * 8 + ks) * 32 + lane];
        uint4 A1 = aF[((mb0 + 1) * 8 + ks) * 32 + lane];
        mma16816(C[0][0], A0, Be.x, Be.y);
        mma16816(C[0][1], A0, Be.z, Be.w);
        mma16816(C[0][2], A0, Bo.x, Bo.y);
        mma16816(C[0][3], A0, Bo.z, Bo.w);
        mma16816(C[1][0], A1, Be.x, Be.y);
        mma16816(C[1][1], A1, Be.z, Be.w);
        mma16816(C[1][2], A1, Bo.x, Bo.y);
        mma16816(C[1][3], A1, Bo.z, Bo.w);
    }
}
// GEMM1 x-lo term: only ksteps 6,7 live in the 2-kstep lo region
__device__ __forceinline__ void gemm_term_lo1(float C[2][4][4],
                                              const uint4* __restrict__ aL,
                                              const uint4* __restrict__ sb,
                                              int mb0, int n16a, int lane) {
#pragma unroll
    for (int ks = 6; ks < 8; ks++) {
        uint4 Be = sb[(ks * 8 + n16a) * 32 + lane];
        uint4 Bo = sb[(ks * 8 + n16a + 1) * 32 + lane];
        uint4 A0 = aL[(mb0 * 2 + (ks - 6)) * 32 + lane];
        uint4 A1 = aL[((mb0 + 1) * 2 + (ks - 6)) * 32 + lane];
        mma16816(C[0][0], A0, Be.x, Be.y);
        mma16816(C[0][1], A0, Be.z, Be.w);
        mma16816(C[0][2], A0, Bo.x, Bo.y);
        mma16816(C[0][3], A0, Bo.z, Bo.w);
        mma16816(C[1][0], A1, Be.x, Be.y);
        mma16816(C[1][1], A1, Be.z, Be.w);
        mma16816(C[1][2], A1, Bo.x, Bo.y);
        mma16816(C[1][3], A1, Bo.z, Bo.w);
    }
}
// GEMM2 stage B: load A fragments from smem ONCE into aR, same MMA order
__device__ __forceinline__ void gemm_term_ldA(float C[2][4][4], uint4 (&aR)[16],
                                              const uint4* __restrict__ aF,
                                              const uint4* __restrict__ sb,
                                              int mb0, int n16a, int lane) {
#pragma unroll
    for (int ks = 0; ks < 8; ks++) {
        uint4 Be = sb[(ks * 8 + n16a) * 32 + lane];
        uint4 Bo = sb[(ks * 8 + n16a + 1) * 32 + lane];
        uint4 A0 = aF[(mb0 * 8 + ks) * 32 + lane];
        uint4 A1 = aF[((mb0 + 1) * 8 + ks) * 32 + lane];
        aR[ks * 2 + 0] = A0;
        aR[ks * 2 + 1] = A1;
        mma16816(C[0][0], A0, Be.x, Be.y);
        mma16816(C[0][1], A0, Be.z, Be.w);
        mma16816(C[0][2], A0, Bo.x, Bo.y);
        mma16816(C[0][3], A0, Bo.z, Bo.w);
        mma16816(C[1][0], A1, Be.x, Be.y);
        mma16816(C[1][1], A1, Be.z, Be.w);
        mma16816(C[1][2], A1, Bo.x, Bo.y);
        mma16816(C[1][3], A1, Bo.z, Bo.w);
    }
}
// GEMM2 stage C: A from registers (no A-LDS at all)
__device__ __forceinline__ void gemm_term_regA(float C[2][4][4],
                                               const uint4 (&aR)[16],
                                               const uint4* __restrict__ sb,
                                               int n16a, int lane) {
#pragma unroll
    for (int ks = 0; ks < 8; ks++) {
        uint4 Be = sb[(ks * 8 + n16a) * 32 + lane];
        uint4 Bo = sb[(ks * 8 + n16a + 1) * 32 + lane];
        const uint4& A0 = aR[ks * 2 + 0];
        const uint4& A1 = aR[ks * 2 + 1];
        mma16816(C[0][0], A0, Be.x, Be.y);
        mma16816(C[0][1], A0, Be.z, Be.w);
        mma16816(C[0][2], A0, Bo.x, Bo.y);
        mma16816(C[0][3], A0, Bo.z, Bo.w);
        mma16816(C[1][0], A1, Be.x, Be.y);
        mma16816(C[1][1], A1, Be.z, Be.w);
        mma16816(C[1][2], A1, Bo.x, Bo.y);
        mma16816(C[1][3], A1, Bo.z, Bo.w);
    }
}

// ---------------------------------------------------------------------------
__global__ void __launch_bounds__(NT, 1)
mlp_hmma_kernel(const float* __restrict__ hole, const float* __restrict__ board,
                const float* __restrict__ b1g, const float* __restrict__ b2g,
                float* __restrict__ out, int Btot)
{
    extern __shared__ __align__(16) unsigned char smp[];
    const int tid = threadIdx.x;
    const int w = tid >> 5, lane = tid & 31;
    const int g = lane >> 2, tg = lane & 3;
    const int row0 = blockIdx.x * BM;

    const uint32_t sm_u = smem_u32(smp);
    uint4* A1h = (uint4*)(smp + A1H_B);
    uint4* A1l = (uint4*)(smp + A1L_B);
    uint4* A2h = (uint4*)(smp + A2H_B);

    // ---- zero A1 fragment regions (40KB) + prologue piece issues ----------
    {
        uint4 z = make_uint4(0, 0, 0, 0);
#pragma unroll 2
        for (int i = tid; i < 2560; i += NT) ((uint4*)smp)[i] = z;
    }
    const uint32_t bb_u = sm_u + BB_B;
    issue_piece(0, bb_u, tid);
    issue_piece(1, bb_u, tid);
    __syncthreads();   // A1 zero visible before feature writes

    // ---- per-row features + card bits -> A1 fragments ---------------------
    if (tid < BM) {
        int r = tid, grow = row0 + r;
        if (grow < Btot) {
            const float* hp = hole + (size_t)grow * 52;
            const float* bp = board + (size_t)grow * 52;
            const __half one = __float2half_rn(1.0f);
            int bsc[4] = {0, 0, 0, 0}, asc[4] = {0, 0, 0, 0};
            int bcount = 0, hcount = 0, pairs_b = 0, pairs_a = 0;
            bool trips_b = false, trips_a = false;
            int pb[17], pa[17];
#pragma unroll
            for (int rk = 0; rk < 13; rk++) {
                int b4 = 0, a4 = 0;
#pragma unroll
                for (int su = 0; su < 4; su++) {
                    int c = rk * 4 + su;
                    int hv = (hp[c] != 0.0f);
                    int bv = (bp[c] != 0.0f);
                    if (hv) *(__half*)(smp + A1H_B + afrag_off(r, c)) = one;
                    if (bv) *(__half*)(smp + A1H_B + afrag_off(r, 52 + c)) = one;
                    b4 += bv; a4 += hv + bv;
                    bcount += bv; hcount += hv;
                    bsc[su] += bv; asc[su] += hv + bv;
                }
                pairs_b += (b4 >= 2); trips_b |= (b4 >= 3);
                pairs_a += (a4 >= 2); trips_a |= (a4 >= 3);
                pb[rk] = (b4 > 0); pa[rk] = (a4 > 0);
            }
#pragma unroll
            for (int i = 13; i < 17; i++) { pb[i] = 0; pa[i] = 0; }

            float strength = trips_b ? 0.8f
                           : (pairs_b >= 2 ? 0.6f : (pairs_b >= 1 ? 0.4f : 0.2f));
            if (bcount == 0) strength = 0.0f;
            int maxbsc = max(max(bsc[0], bsc[1]), max(bsc[2], bsc[3]));
            float flush_b = (maxbsc >= 3 && bcount > 0) ? 1.0f : 0.0f;
            bool sb = false;
#pragma unroll
            for (int j = 0; j < 13; j++) {
                int ww = pb[j] + pb[j + 1] + pb[j + 2] + pb[j + 3] + pb[j + 4];
                if (ww >= 3) sb = true;
            }
            float straight_b = (sb && bcount > 0) ? 1.0f : 0.0f;
            float valid = (hcount >= 2 && bcount >= 1) ? 1.0f : 0.0f;
            int msc = max(max(asc[0], asc[1]), max(asc[2], asc[3]));
            float flush_draw = (msc == 4) ? 1.0f : 0.0f;
            float flush_outs = fmaxf(0.0f, 13.0f - (float)msc) / 13.0f;
            bool found = false; int c4_at = 0;
#pragma unroll
            for (int j = 0; j < 13; j++) {
                int c5 = pa[j] + pa[j + 1] + pa[j + 2] + pa[j + 3] + pa[j + 4];
                bool q = (pa[j] > 0) && (c5 >= 4);
                if (q && !found) {
                    found = true;
                    c4_at = pa[j] + pa[j + 1] + pa[j + 2] + pa[j + 3];
                }
            }
            float sd = found ? 1.0f : 0.0f;
            float so = found ? (c4_at >= 4 ? 0.4f : 0.2f) : 0.0f;
            float total_outs = flush_draw * flush_outs * 9.0f + sd * so * 8.0f;
            float remaining = 52.0f - (float)(hcount + bcount);
            float equity = (remaining > 0.0f)
                ? fminf(1.0f, total_outs / fmaxf(remaining, 1.0f)) : 0.0f;

            float feats[15];
            feats[0] = strength; feats[1] = flush_b; feats[2] = straight_b;
            feats[3] = (bcount == 0) ? 1.0f : 0.0f;
            feats[4] = (bcount == 3) ? 1.0f : 0.0f;
            feats[5] = (bcount == 4) ? 1.0f : 0.0f;
            feats[6] = (bcount == 5) ? 1.0f : 0.0f;
            feats[7]  = valid * flush_draw;
            feats[8]  = valid * flush_outs;
            feats[9]  = valid * sd;
            feats[10] = valid * so;
            feats[11] = valid * equity;
            feats[12] = valid * ((pairs_a >= 1) ? 1.0f : 0.0f);
            feats[13] = valid * (trips_a ? 1.0f : 0.0f);
            feats[14] = valid * ((pairs_a >= 2) ? 1.0f : 0.0f);
#pragma unroll
            for (int t = 0; t < 15; t++) {
                float f = feats[t];
                float fh = f16rt(f);
                int cl = 104 + t;
                *(__half*)(smp + A1H_B + afrag_off(r, cl)) = __float2half_rn(f);
                *(__half*)(smp + A1L_B + lofrag_off(r, cl)) =
                    __float2half_rn(f - fh);
            }
        }
    }

    const int mb0 = (w >> 2) * 2;   // warp M-range: rows mb0*16 .. +32
    const int nq  = (w & 3);        // warp N-range: n8 blocks nq*4 .. +4
    const int n16a = nq * 2;

    float C2[2][2][4][4];           // [half][mbi][j][reg]
#pragma unroll
    for (int h = 0; h < 2; h++)
#pragma unroll
        for (int mi = 0; mi < 2; mi++)
#pragma unroll
            for (int j = 0; j < 4; j++)
#pragma unroll
                for (int q = 0; q < 4; q++) C2[h][mi][j][q] = 0.0f;

    int p = 0;
    for (int c = 0; c < 8; c++) {
        float C1[2][4][4];
#pragma unroll
        for (int mi = 0; mi < 2; mi++)
#pragma unroll
            for (int j = 0; j < 4; j++)
#pragma unroll
                for (int q = 0; q < 4; q++) C1[mi][j][q] = 0.0f;

        // stage A: piece 3c (W1) — wait; ONE sync; issue p+2; compute
        CP_WAIT1(); __syncthreads();
        issue_piece(p + 2, bb_u, tid);
        {
            const uint4* sb = (const uint4*)(smp + BB_B + piece_slot(p));
            gemm_term(C1, A1h, sb, mb0, n16a, lane);
            gemm_term_lo1(C1, A1l, sb, mb0, n16a, lane);
        }
        p++;

        // epilogue: add b1, relu, fp16 round, store as A2 fragments
#pragma unroll
        for (int mi = 0; mi < 2; mi++) {
#pragma unroll
            for (int jp = 0; jp < 2; jp++) {
                int ksg = nq * 2 + jp;
                int n0e = (nq * 4 + 2 * jp) * 8 + tg * 2;
                float2 b1e = *(const float2*)(b1g + c * 128 + n0e);
                float2 b1o = *(const float2*)(b1g + c * 128 + n0e + 8);
                float* fe = C1[mi][2 * jp];
                float* fo = C1[mi][2 * jp + 1];
                float e0 = fmaxf(fe[0] + b1e.x, 0.0f);
                float e1 = fmaxf(fe[1] + b1e.y, 0.0f);
                float e2 = fmaxf(fe[2] + b1e.x, 0.0f);
                float e3 = fmaxf(fe[3] + b1e.y, 0.0f);
                float o0 = fmaxf(fo[0] + b1o.x, 0.0f);
                float o1 = fmaxf(fo[1] + b1o.y, 0.0f);
                float o2 = fmaxf(fo[2] + b1o.x, 0.0f);
                float o3 = fmaxf(fo[3] + b1o.y, 0.0f);
                uint4 hv;
                hv.x = pack_f16(e0, e1); hv.y = pack_f16(e2, e3);
                hv.z = pack_f16(o0, o1); hv.w = pack_f16(o2, o3);
                int idx = ((mb0 + mi) * 8 + ksg) * 32 + lane;
                A2h[idx] = hv;
            }
        }

        // stage B: piece 3c+1 (W2 half0) — A loaded once into regs
        uint4 aR[16];
        CP_WAIT1(); __syncthreads();
        issue_piece(p + 2, bb_u, tid);
        gemm_term_ldA(C2[0], aR, A2h,
                      (const uint4*)(smp + BB_B + piece_slot(p)),
                      mb0, n16a, lane);
        p++;

        // stage C: piece 3c+2 (W2 half1) — A from registers, zero A-LDS
        CP_WAIT1(); __syncthreads();
        issue_piece(p + 2, bb_u, tid);
        gemm_term_regA(C2[1], aR,
                       (const uint4*)(smp + BB_B + piece_slot(p)),
                       n16a, lane);
        p++;
    }

    // ---- final epilogue: C2 + b2 -> out -----------------------------------
#pragma unroll
    for (int h = 0; h < 2; h++) {
#pragma unroll
        for (int mi = 0; mi < 2; mi++) {
            int r0 = row0 + (mb0 + mi) * 16 + g;
#pragma unroll
            for (int j = 0; j < 4; j++) {
                int n0 = h * 128 + (nq * 4 + j) * 8 + tg * 2;
                float2 bb = *(const float2*)(b2g + n0);
                float* cc = C2[h][mi][j];
                if (r0 < Btot) {
                    float2 v = make_float2(cc[0] + bb.x, cc[1] + bb.y);
                    *(float2*)(out + (size_t)r0 * OUTDIM + n0) = v;
                }
                if (r0 + 8 < Btot) {
                    float2 v = make_float2(cc[2] + bb.x, cc[3] + bb.y);
                    *(float2*)(out + (size_t)(r0 + 8) * OUTDIM + n0) = v;
                }
            }
        }
    }
}

// ---------------------------------------------------------------------------
extern "C" void kernel_launch(void* const* d_in, const int* in_sizes, int n_in,
                              void* d_out, int out_size)
{
    const float* hole  = (const float*)d_in[0];
    const float* board = (const float*)d_in[1];
    const float* W1    = (const float*)d_in[2];
    const float* b1    = (const float*)d_in[3];
    const float* W2    = (const float*)d_in[4];
    const float* b2    = (const float*)d_in[5];
    float* out = (float*)d_out;

    int B = in_sizes[0] / 52;
    int blocks = (B + BM - 1) / BM;

    prep_w1<<<(8 * 8192 + 255) / 256, 256>>>(W1);
    prep_w2<<<(16 * 8192 + 255) / 256, 256>>>(W2);

    cudaFuncSetAttribute(mlp_hmma_kernel,
                         cudaFuncAttributeMaxDynamicSharedMemorySize, SMEMB);
    mlp_hmma_kernel<<<blocks, NT, SMEMB>>>(hole, board, b1, b2, out, B);
}

// round 15
// speedup vs baseline: 1.0746x; 1.0746x over previous
#include <cuda_runtime.h>
#include <cuda_fp16.h>
#include <cstdint>

// ===========================================================================
// Fused poker-feature MLP via mma.sync (HMMA fp16).
//   out[B,256] = relu(x @ W1 + b1) @ W2 + b2,  x = [hole|board|feats] (119)
//
// R14 = R12 (360.9us; BM=128, NT=512, 3-slot ring, one sync/stage) with the
//       GEMM1 lo-term fused into the hi ks-loop for ks>=6, reusing the
//       already-loaded Be/Bo registers (-4 LDS.128/warp/chunk, zero extra
//       register pressure).  Accumulation order pre-validated by R11
//       (rel_err 3.682252e-4).
// Math: GEMM1 = Ah*B + featlo*B ; GEMM2 = Ah*B per half (A in smem).
// ===========================================================================

#define NT     512
#define BM     128
#define IND    119
#define HID    1024
#define OUTDIM 256

// smem byte offsets
#define A1H_B 0u        // [mb8][ks8][lane32][16B] = 32KB
#define A1L_B 32768u    // [mb8][ks2][lane32][16B] = 8KB (k 96..127 only)
#define A2H_B 40960u    // [mb8][ks8][lane32][16B] = 32KB
#define BB_B  73728u    // 3 x 32KB piece slots
#define SMEMB 172032u

#define NPIECES 24      // 8 chunks x 3 pieces (W1, W2h0, W2h1)

// fragment-ordered weight images (fp16 hi only)
__device__ __align__(16) unsigned char gW1frag[8 * 32768];   // [c]
__device__ __align__(16) unsigned char gW2frag[16 * 32768];  // [c][half]

// ---------------------------------------------------------------------------
__device__ __forceinline__ unsigned pack_f16(float a, float b) {
    __half2 t = __floats2half2_rn(a, b);
    return *(unsigned*)&t;
}
__device__ __forceinline__ float f16rt(float a) {
    return __half2float(__float2half_rn(a));
}
__device__ __forceinline__ uint32_t smem_u32(const void* p) {
    uint32_t a;
    asm("{ .reg .u64 t; cvta.to.shared.u64 t, %1; cvt.u32.u64 %0, t; }"
        : "=r"(a) : "l"(p));
    return a;
}
__device__ __forceinline__ void mma16816(float c[4], const uint4& A,
                                         unsigned b0, unsigned b1) {
    asm volatile(
        "mma.sync.aligned.m16n8k16.row.col.f32.f16.f16.f32 "
        "{%0,%1,%2,%3}, {%4,%5,%6,%7}, {%8,%9}, {%0,%1,%2,%3};\n"
        : "+f"(c[0]), "+f"(c[1]), "+f"(c[2]), "+f"(c[3])
        : "r"(A.x), "r"(A.y), "r"(A.z), "r"(A.w), "r"(b0), "r"(b1));
}
#define CP_WAIT1() asm volatile("cp.async.wait_group 1;" ::: "memory")

// byte offset of element (row r, col cl) in an A-fragment region (8 mblks)
__device__ __forceinline__ uint32_t afrag_off(int r, int cl) {
    int mb = r >> 4, i = r & 15, ks = cl >> 4, jj = cl & 15;
    int lane = ((i & 7) << 2) + ((jj & 7) >> 1);
    int reg = (i >> 3) + ((jj >> 3) << 1);
    return ((((mb << 3) + ks) << 5) + lane) * 16u + (reg << 2) + ((jj & 1) << 1);
}
// 2-kstep lo region (k 96..127)
__device__ __forceinline__ uint32_t lofrag_off(int r, int cl) {
    int mb = r >> 4, i = r & 15, ks = (cl >> 4) - 6, jj = cl & 15;
    int lane = ((i & 7) << 2) + ((jj & 7) >> 1);
    int reg = (i >> 3) + ((jj >> 3) << 1);
    return ((((mb << 1) + ks) << 5) + lane) * 16u + (reg << 2) + ((jj & 1) << 1);
}

// ---------------------------------------------------------------------------
// Prep: cook fp16 fragment images (layout identical to R9/R12).
// ---------------------------------------------------------------------------
__global__ void prep_w1(const float* __restrict__ W1) {
    int id = blockIdx.x * blockDim.x + threadIdx.x;
    if (id >= 8 * 8192) return;
    int c = id >> 13, q = id & 8191;
    int ks = q >> 10, n16 = (q >> 7) & 7, lane = (q >> 2) & 31, j = q & 3;
    int n8 = n16 * 2 + (j >> 1), breg = j & 1;
    int k = ks * 16 + (lane & 3) * 2 + breg * 8;
    int n = n8 * 8 + (lane >> 2);
    float v0 = (k < IND)     ? W1[k * HID + c * 128 + n]       : 0.0f;
    float v1 = (k + 1 < IND) ? W1[(k + 1) * HID + c * 128 + n] : 0.0f;
    ((unsigned*)gW1frag)[c * 8192 + q] = pack_f16(v0, v1);
}
__global__ void prep_w2(const float* __restrict__ W2) {
    int id = blockIdx.x * blockDim.x + threadIdx.x;
    if (id >= 16 * 8192) return;
    int pi = id >> 13, q = id & 8191;
    int c = pi >> 1, half = pi & 1;
    int ks = q >> 10, n16 = (q >> 7) & 7, lane = (q >> 2) & 31, j = q & 3;
    int n8 = n16 * 2 + (j >> 1), breg = j & 1;
    int k = ks * 16 + (lane & 3) * 2 + breg * 8;
    int n = n8 * 8 + (lane >> 2);
    float v0 = W2[(c * 128 + k) * OUTDIM + half * 128 + n];
    float v1 = W2[(c * 128 + k + 1) * OUTDIM + half * 128 + n];
    ((unsigned*)gW2frag)[pi * 8192 + q] = pack_f16(v0, v1);
}

// ---------------------------------------------------------------------------
__device__ __forceinline__ const unsigned char* piece_src(int p) {
    int c = p / 3, t = p % 3;
    if (t == 0) return gW1frag + (size_t)c * 32768u;
    return gW2frag + (size_t)((c << 1) + (t - 1)) * 32768u;
}
// slot for piece p in the 3-slot ring
__device__ __forceinline__ uint32_t piece_slot(int p) {
    return (uint32_t)(p % 3) * 32768u;
}
__device__ __forceinline__ void issue_piece(int p, uint32_t bb_u32, int tid) {
    if (p < NPIECES) {
        const unsigned char* src = piece_src(p) + tid * 64;
        uint32_t dst = bb_u32 + piece_slot(p) + (uint32_t)tid * 64u;
#pragma unroll
        for (int i = 0; i < 4; i++)
            asm volatile("cp.async.cg.shared.global [%0], [%1], 16;"
                         :: "r"(dst + i * 16), "l"(src + i * 16));
    }
    asm volatile("cp.async.commit_group;" ::: "memory");
}

// GEMM1 fused: hi term full-K, lo term for ks>=6 reusing the same B regs
__device__ __forceinline__ void gemm1_fused(float C[2][4][4],
                                            const uint4* __restrict__ aF,
                                            const uint4* __restrict__ aL,
                                            const uint4* __restrict__ sb,
                                            int mb0, int n16a, int lane) {
#pragma unroll
    for (int ks = 0; ks < 8; ks++) {
        uint4 Be = sb[(ks * 8 + n16a) * 32 + lane];
        uint4 Bo = sb[(ks * 8 + n16a + 1) * 32 + lane];
        uint4 A0 = aF[(mb0 * 8 + ks) * 32 + lane];
        uint4 A1 = aF[((mb0 + 1) * 8 + ks) * 32 + lane];
        mma16816(C[0][0], A0, Be.x, Be.y);
        mma16816(C[0][1], A0, Be.z, Be.w);
        mma16816(C[0][2], A0, Bo.x, Bo.y);
        mma16816(C[0][3], A0, Bo.z, Bo.w);
        mma16816(C[1][0], A1, Be.x, Be.y);
        mma16816(C[1][1], A1, Be.z, Be.w);
        mma16816(C[1][2], A1, Bo.x, Bo.y);
        mma16816(C[1][3], A1, Bo.z, Bo.w);
        if (ks >= 6) {
            uint4 L0 = aL[(mb0 * 2 + (ks - 6)) * 32 + lane];
            uint4 L1 = aL[((mb0 + 1) * 2 + (ks - 6)) * 32 + lane];
            mma16816(C[0][0], L0, Be.x, Be.y);
            mma16816(C[0][1], L0, Be.z, Be.w);
            mma16816(C[0][2], L0, Bo.x, Bo.y);
            mma16816(C[0][3], L0, Bo.z, Bo.w);
            mma16816(C[1][0], L1, Be.x, Be.y);
            mma16816(C[1][1], L1, Be.z, Be.w);
            mma16816(C[1][2], L1, Bo.x, Bo.y);
            mma16816(C[1][3], L1, Bo.z, Bo.w);
        }
    }
}

// full-K single-A term with smem A (GEMM2)
__device__ __forceinline__ void gemm_term(float C[2][4][4],
                                          const uint4* __restrict__ aF,
                                          const uint4* __restrict__ sb,
                                          int mb0, int n16a, int lane) {
#pragma unroll
    for (int ks = 0; ks < 8; ks++) {
        uint4 Be = sb[(ks * 8 + n16a) * 32 + lane];
        uint4 Bo = sb[(ks * 8 + n16a + 1) * 32 + lane];
        uint4 A0 = aF[(mb0 * 8 + ks) * 32 + lane];
        uint4 A1 = aF[((mb0 + 1) * 8 + ks) * 32 + lane];
        mma16816(C[0][0], A0, Be.x, Be.y);
        mma16816(C[0][1], A0, Be.z, Be.w);
        mma16816(C[0][2], A0, Bo.x, Bo.y);
        mma16816(C[0][3], A0, Bo.z, Bo.w);
        mma16816(C[1][0], A1, Be.x, Be.y);
        mma16816(C[1][1], A1, Be.z, Be.w);
        mma16816(C[1][2], A1, Bo.x, Bo.y);
        mma16816(C[1][3], A1, Bo.z, Bo.w);
    }
}

// ---------------------------------------------------------------------------
__global__ void __launch_bounds__(NT, 1)
mlp_hmma_kernel(const float* __restrict__ hole, const float* __restrict__ board,
                const float* __restrict__ b1g, const float* __restrict__ b2g,
                float* __restrict__ out, int Btot)
{
    extern __shared__ __align__(16) unsigned char smp[];
    const int tid = threadIdx.x;
    const int w = tid >> 5, lane = tid & 31;
    const int g = lane >> 2, tg = lane & 3;
    const int row0 = blockIdx.x * BM;

    const uint32_t sm_u = smem_u32(smp);
    uint4* A1h = (uint4*)(smp + A1H_B);
    uint4* A1l = (uint4*)(smp + A1L_B);
    uint4* A2h = (uint4*)(smp + A2H_B);

    // ---- zero A1 fragment regions (40KB) + prologue piece issues ----------
    {
        uint4 z = make_uint4(0, 0, 0, 0);
#pragma unroll 2
        for (int i = tid; i < 2560; i += NT) ((uint4*)smp)[i] = z;
    }
    const uint32_t bb_u = sm_u + BB_B;
    issue_piece(0, bb_u, tid);
    issue_piece(1, bb_u, tid);
    __syncthreads();   // A1 zero visible before feature writes

    // ---- per-row features + card bits -> A1 fragments ---------------------
    if (tid < BM) {
        int r = tid, grow = row0 + r;
        if (grow < Btot) {
            const float* hp = hole + (size_t)grow * 52;
            const float* bp = board + (size_t)grow * 52;
            const __half one = __float2half_rn(1.0f);
            int bsc[4] = {0, 0, 0, 0}, asc[4] = {0, 0, 0, 0};
            int bcount = 0, hcount = 0, pairs_b = 0, pairs_a = 0;
            bool trips_b = false, trips_a = false;
            int pb[17], pa[17];
#pragma unroll
            for (int rk = 0; rk < 13; rk++) {
                int b4 = 0, a4 = 0;
#pragma unroll
                for (int su = 0; su < 4; su++) {
                    int c = rk * 4 + su;
                    int hv = (hp[c] != 0.0f);
                    int bv = (bp[c] != 0.0f);
                    if (hv) *(__half*)(smp + A1H_B + afrag_off(r, c)) = one;
                    if (bv) *(__half*)(smp + A1H_B + afrag_off(r, 52 + c)) = one;
                    b4 += bv; a4 += hv + bv;
                    bcount += bv; hcount += hv;
                    bsc[su] += bv; asc[su] += hv + bv;
                }
                pairs_b += (b4 >= 2); trips_b |= (b4 >= 3);
                pairs_a += (a4 >= 2); trips_a |= (a4 >= 3);
                pb[rk] = (b4 > 0); pa[rk] = (a4 > 0);
            }
#pragma unroll
            for (int i = 13; i < 17; i++) { pb[i] = 0; pa[i] = 0; }

            float strength = trips_b ? 0.8f
                           : (pairs_b >= 2 ? 0.6f : (pairs_b >= 1 ? 0.4f : 0.2f));
            if (bcount == 0) strength = 0.0f;
            int maxbsc = max(max(bsc[0], bsc[1]), max(bsc[2], bsc[3]));
            float flush_b = (maxbsc >= 3 && bcount > 0) ? 1.0f : 0.0f;
            bool sb = false;
#pragma unroll
            for (int j = 0; j < 13; j++) {
                int ww = pb[j] + pb[j + 1] + pb[j + 2] + pb[j + 3] + pb[j + 4];
                if (ww >= 3) sb = true;
            }
            float straight_b = (sb && bcount > 0) ? 1.0f : 0.0f;
            float valid = (hcount >= 2 && bcount >= 1) ? 1.0f : 0.0f;
            int msc = max(max(asc[0], asc[1]), max(asc[2], asc[3]));
            float flush_draw = (msc == 4) ? 1.0f : 0.0f;
            float flush_outs = fmaxf(0.0f, 13.0f - (float)msc) / 13.0f;
            bool found = false; int c4_at = 0;
#pragma unroll
            for (int j = 0; j < 13; j++) {
                int c5 = pa[j] + pa[j + 1] + pa[j + 2] + pa[j + 3] + pa[j + 4];
                bool q = (pa[j] > 0) && (c5 >= 4);
                if (q && !found) {
                    found = true;
                    c4_at = pa[j] + pa[j + 1] + pa[j + 2] + pa[j + 3];
                }
            }
            float sd = found ? 1.0f : 0.0f;
            float so = found ? (c4_at >= 4 ? 0.4f : 0.2f) : 0.0f;
            float total_outs = flush_draw * flush_outs * 9.0f + sd * so * 8.0f;
            float remaining = 52.0f - (float)(hcount + bcount);
            float equity = (remaining > 0.0f)
                ? fminf(1.0f, total_outs / fmaxf(remaining, 1.0f)) : 0.0f;

            float feats[15];
            feats[0] = strength; feats[1] = flush_b; feats[2] = straight_b;
            feats[3] = (bcount == 0) ? 1.0f : 0.0f;
            feats[4] = (bcount == 3) ? 1.0f : 0.0f;
            feats[5] = (bcount == 4) ? 1.0f : 0.0f;
            feats[6] = (bcount == 5) ? 1.0f : 0.0f;
            feats[7]  = valid * flush_draw;
            feats[8]  = valid * flush_outs;
            feats[9]  = valid * sd;
            feats[10] = valid * so;
            feats[11] = valid * equity;
            feats[12] = valid * ((pairs_a >= 1) ? 1.0f : 0.0f);
            feats[13] = valid * (trips_a ? 1.0f : 0.0f);
            feats[14] = valid * ((pairs_a >= 2) ? 1.0f : 0.0f);
#pragma unroll
            for (int t = 0; t < 15; t++) {
                float f = feats[t];
                float fh = f16rt(f);
                int cl = 104 + t;
                *(__half*)(smp + A1H_B + afrag_off(r, cl)) = __float2half_rn(f);
                *(__half*)(smp + A1L_B + lofrag_off(r, cl)) =
                    __float2half_rn(f - fh);
            }
        }
    }

    const int mb0 = (w >> 2) * 2;   // warp M-range: rows mb0*16 .. +32
    const int nq  = (w & 3);        // warp N-range: n8 blocks nq*4 .. +4
    const int n16a = nq * 2;

    float C2[2][2][4][4];           // [half][mbi][j][reg]
#pragma unroll
    for (int h = 0; h < 2; h++)
#pragma unroll
        for (int mi = 0; mi < 2; mi++)
#pragma unroll
            for (int j = 0; j < 4; j++)
#pragma unroll
                for (int q = 0; q < 4; q++) C2[h][mi][j][q] = 0.0f;

    int p = 0;
    for (int c = 0; c < 8; c++) {
        float C1[2][4][4];
#pragma unroll
        for (int mi = 0; mi < 2; mi++)
#pragma unroll
            for (int j = 0; j < 4; j++)
#pragma unroll
                for (int q = 0; q < 4; q++) C1[mi][j][q] = 0.0f;

        // stage A: piece 3c (W1) — wait; ONE sync; issue p+2; fused compute
        CP_WAIT1(); __syncthreads();
        issue_piece(p + 2, bb_u, tid);
        gemm1_fused(C1, A1h, A1l,
                    (const uint4*)(smp + BB_B + piece_slot(p)),
                    mb0, n16a, lane);
        p++;

        // epilogue: add b1, relu, fp16 round, store as A2 fragments
#pragma unroll
        for (int mi = 0; mi < 2; mi++) {
#pragma unroll
            for (int jp = 0; jp < 2; jp++) {
                int ksg = nq * 2 + jp;
                int n0e = (nq * 4 + 2 * jp) * 8 + tg * 2;
                float2 b1e = *(const float2*)(b1g + c * 128 + n0e);
                float2 b1o = *(const float2*)(b1g + c * 128 + n0e + 8);
                float* fe = C1[mi][2 * jp];
                float* fo = C1[mi][2 * jp + 1];
                float e0 = fmaxf(fe[0] + b1e.x, 0.0f);
                float e1 = fmaxf(fe[1] + b1e.y, 0.0f);
                float e2 = fmaxf(fe[2] + b1e.x, 0.0f);
                float e3 = fmaxf(fe[3] + b1e.y, 0.0f);
                float o0 = fmaxf(fo[0] + b1o.x, 0.0f);
                float o1 = fmaxf(fo[1] + b1o.y, 0.0f);
                float o2 = fmaxf(fo[2] + b1o.x, 0.0f);
                float o3 = fmaxf(fo[3] + b1o.y, 0.0f);
                uint4 hv;
                hv.x = pack_f16(e0, e1); hv.y = pack_f16(e2, e3);
                hv.z = pack_f16(o0, o1); hv.w = pack_f16(o2, o3);
                int idx = ((mb0 + mi) * 8 + ksg) * 32 + lane;
                A2h[idx] = hv;
            }
        }

        // stage B: piece 3c+1 (W2 half0)
        CP_WAIT1(); __syncthreads();
        issue_piece(p + 2, bb_u, tid);
        gemm_term(C2[0], A2h,
                  (const uint4*)(smp + BB_B + piece_slot(p)), mb0, n16a, lane);
        p++;

        // stage C: piece 3c+2 (W2 half1)
        CP_WAIT1(); __syncthreads();
        issue_piece(p + 2, bb_u, tid);
        gemm_term(C2[1], A2h,
                  (const uint4*)(smp + BB_B + piece_slot(p)), mb0, n16a, lane);
        p++;
    }

    // ---- final epilogue: C2 + b2 -> out -----------------------------------
#pragma unroll
    for (int h = 0; h < 2; h++) {
#pragma unroll
        for (int mi = 0; mi < 2; mi++) {
            int r0 = row0 + (mb0 + mi) * 16 + g;
#pragma unroll
            for (int j = 0; j < 4; j++) {
                int n0 = h * 128 + (nq * 4 + j) * 8 + tg * 2;
                float2 bb = *(const float2*)(b2g + n0);
                float* cc = C2[h][mi][j];
                if (r0 < Btot) {
                    float2 v = make_float2(cc[0] + bb.x, cc[1] + bb.y);
                    *(float2*)(out + (size_t)r0 * OUTDIM + n0) = v;
                }
                if (r0 + 8 < Btot) {
                    float2 v = make_float2(cc[2] + bb.x, cc[3] + bb.y);
                    *(float2*)(out + (size_t)(r0 + 8) * OUTDIM + n0) = v;
                }
            }
        }
    }
}

// ---------------------------------------------------------------------------
extern "C" void kernel_launch(void* const* d_in, const int* in_sizes, int n_in,
                              void* d_out, int out_size)
{
    const float* hole  = (const float*)d_in[0];
    const float* board = (const float*)d_in[1];
    const float* W1    = (const float*)d_in[2];
    const float* b1    = (const float*)d_in[3];
    const float* W2    = (const float*)d_in[4];
    const float* b2    = (const float*)d_in[5];
    float* out = (float*)d_out;

    int B = in_sizes[0] / 52;
    int blocks = (B + BM - 1) / BM;

    prep_w1<<<(8 * 8192 + 255) / 256, 256>>>(W1);
    prep_w2<<<(16 * 8192 + 255) / 256, 256>>>(W2);

    cudaFuncSetAttribute(mlp_hmma_kernel,
                         cudaFuncAttributeMaxDynamicSharedMemorySize, SMEMB);
    mlp_hmma_kernel<<<blocks, NT, SMEMB>>>(hole, board, b1, b2, out, B);
}

// round 16
// speedup vs baseline: 1.0996x; 1.0233x over previous
#include <cuda_runtime.h>
#include <cuda_fp16.h>
#include <cstdint>

// ===========================================================================
// Fused poker-feature MLP via mma.sync (HMMA fp16).
//   out[B,256] = relu(x @ W1 + b1) @ W2 + b2,  x = [hole|board|feats] (119)
//
// R15 = R12 (360.9us; BM=128, NT=512, 3-slot ring, one sync/stage) with the
//       chunk epilogue's b1 reads moved off the critical path:
//   - b1 (4KB) staged into smem once during the prologue
//   - mi-invariant b1 loads hoisted out of the mi loop (half the loads)
// Math identical to R12: GEMM1 = Ah*B + featlo*B (separate passes);
// GEMM2 = Ah*B per half.  rel_err must equal 3.682313e-4 exactly.
// ===========================================================================

#define NT     512
#define BM     128
#define IND    119
#define HID    1024
#define OUTDIM 256

// smem byte offsets
#define A1H_B 0u        // [mb8][ks8][lane32][16B] = 32KB
#define A1L_B 32768u    // [mb8][ks2][lane32][16B] = 8KB (k 96..127 only)
#define A2H_B 40960u    // [mb8][ks8][lane32][16B] = 32KB
#define BB_B  73728u    // 3 x 32KB piece slots
#define B1S_B 172032u   // staged b1: 1024 floats = 4KB
#define SMEMB 176128u

#define NPIECES 24      // 8 chunks x 3 pieces (W1, W2h0, W2h1)

// fragment-ordered weight images (fp16 hi only)
__device__ __align__(16) unsigned char gW1frag[8 * 32768];   // [c]
__device__ __align__(16) unsigned char gW2frag[16 * 32768];  // [c][half]

// ---------------------------------------------------------------------------
__device__ __forceinline__ unsigned pack_f16(float a, float b) {
    __half2 t = __floats2half2_rn(a, b);
    return *(unsigned*)&t;
}
__device__ __forceinline__ float f16rt(float a) {
    return __half2float(__float2half_rn(a));
}
__device__ __forceinline__ uint32_t smem_u32(const void* p) {
    uint32_t a;
    asm("{ .reg .u64 t; cvta.to.shared.u64 t, %1; cvt.u32.u64 %0, t; }"
        : "=r"(a) : "l"(p));
    return a;
}
__device__ __forceinline__ void mma16816(float c[4], const uint4& A,
                                         unsigned b0, unsigned b1) {
    asm volatile(
        "mma.sync.aligned.m16n8k16.row.col.f32.f16.f16.f32 "
        "{%0,%1,%2,%3}, {%4,%5,%6,%7}, {%8,%9}, {%0,%1,%2,%3};\n"
        : "+f"(c[0]), "+f"(c[1]), "+f"(c[2]), "+f"(c[3])
        : "r"(A.x), "r"(A.y), "r"(A.z), "r"(A.w), "r"(b0), "r"(b1));
}
#define CP_WAIT1() asm volatile("cp.async.wait_group 1;" ::: "memory")

// byte offset of element (row r, col cl) in an A-fragment region (8 mblks)
__device__ __forceinline__ uint32_t afrag_off(int r, int cl) {
    int mb = r >> 4, i = r & 15, ks = cl >> 4, jj = cl & 15;
    int lane = ((i & 7) << 2) + ((jj & 7) >> 1);
    int reg = (i >> 3) + ((jj >> 3) << 1);
    return ((((mb << 3) + ks) << 5) + lane) * 16u + (reg << 2) + ((jj & 1) << 1);
}
// 2-kstep lo region (k 96..127)
__device__ __forceinline__ uint32_t lofrag_off(int r, int cl) {
    int mb = r >> 4, i = r & 15, ks = (cl >> 4) - 6, jj = cl & 15;
    int lane = ((i & 7) << 2) + ((jj & 7) >> 1);
    int reg = (i >> 3) + ((jj >> 3) << 1);
    return ((((mb << 1) + ks) << 5) + lane) * 16u + (reg << 2) + ((jj & 1) << 1);
}

// ---------------------------------------------------------------------------
// Prep: cook fp16 fragment images (layout identical to R9/R12).
// ---------------------------------------------------------------------------
__global__ void prep_w1(const float* __restrict__ W1) {
    int id = blockIdx.x * blockDim.x + threadIdx.x;
    if (id >= 8 * 8192) return;
    int c = id >> 13, q = id & 8191;
    int ks = q >> 10, n16 = (q >> 7) & 7, lane = (q >> 2) & 31, j = q & 3;
    int n8 = n16 * 2 + (j >> 1), breg = j & 1;
    int k = ks * 16 + (lane & 3) * 2 + breg * 8;
    int n = n8 * 8 + (lane >> 2);
    float v0 = (k < IND)     ? W1[k * HID + c * 128 + n]       : 0.0f;
    float v1 = (k + 1 < IND) ? W1[(k + 1) * HID + c * 128 + n] : 0.0f;
    ((unsigned*)gW1frag)[c * 8192 + q] = pack_f16(v0, v1);
}
__global__ void prep_w2(const float* __restrict__ W2) {
    int id = blockIdx.x * blockDim.x + threadIdx.x;
    if (id >= 16 * 8192) return;
    int pi = id >> 13, q = id & 8191;
    int c = pi >> 1, half = pi & 1;
    int ks = q >> 10, n16 = (q >> 7) & 7, lane = (q >> 2) & 31, j = q & 3;
    int n8 = n16 * 2 + (j >> 1), breg = j & 1;
    int k = ks * 16 + (lane & 3) * 2 + breg * 8;
    int n = n8 * 8 + (lane >> 2);
    float v0 = W2[(c * 128 + k) * OUTDIM + half * 128 + n];
    float v1 = W2[(c * 128 + k + 1) * OUTDIM + half * 128 + n];
    ((unsigned*)gW2frag)[pi * 8192 + q] = pack_f16(v0, v1);
}

// ---------------------------------------------------------------------------
__device__ __forceinline__ const unsigned char* piece_src(int p) {
    int c = p / 3, t = p % 3;
    if (t == 0) return gW1frag + (size_t)c * 32768u;
    return gW2frag + (size_t)((c << 1) + (t - 1)) * 32768u;
}
// slot for piece p in the 3-slot ring
__device__ __forceinline__ uint32_t piece_slot(int p) {
    return (uint32_t)(p % 3) * 32768u;
}
__device__ __forceinline__ void issue_piece(int p, uint32_t bb_u32, int tid) {
    if (p < NPIECES) {
        const unsigned char* src = piece_src(p) + tid * 64;
        uint32_t dst = bb_u32 + piece_slot(p) + (uint32_t)tid * 64u;
#pragma unroll
        for (int i = 0; i < 4; i++)
            asm volatile("cp.async.cg.shared.global [%0], [%1], 16;"
                         :: "r"(dst + i * 16), "l"(src + i * 16));
    }
    asm volatile("cp.async.commit_group;" ::: "memory");
}

// full-K single-A term: C[2][4][4] += A * B
__device__ __forceinline__ void gemm_term(float C[2][4][4],
                                          const uint4* __restrict__ aF,
                                          const uint4* __restrict__ sb,
                                          int mb0, int n16a, int lane) {
#pragma unroll
    for (int ks = 0; ks < 8; ks++) {
        uint4 Be = sb[(ks * 8 + n16a) * 32 + lane];
        uint4 Bo = sb[(ks * 8 + n16a + 1) * 32 + lane];
        uint4 A0 = aF[(mb0 * 8 + ks) * 32 + lane];
        uint4 A1 = aF[((mb0 + 1) * 8 + ks) * 32 + lane];
        mma16816(C[0][0], A0, Be.x, Be.y);
        mma16816(C[0][1], A0, Be.z, Be.w);
        mma16816(C[0][2], A0, Bo.x, Bo.y);
        mma16816(C[0][3], A0, Bo.z, Bo.w);
        mma16816(C[1][0], A1, Be.x, Be.y);
        mma16816(C[1][1], A1, Be.z, Be.w);
        mma16816(C[1][2], A1, Bo.x, Bo.y);
        mma16816(C[1][3], A1, Bo.z, Bo.w);
    }
}
// GEMM1 x-lo term: only ksteps 6,7 live in the 2-kstep lo region
__device__ __forceinline__ void gemm_term_lo1(float C[2][4][4],
                                              const uint4* __restrict__ aL,
                                              const uint4* __restrict__ sb,
                                              int mb0, int n16a, int lane) {
#pragma unroll
    for (int ks = 6; ks < 8; ks++) {
        uint4 Be = sb[(ks * 8 + n16a) * 32 + lane];
        uint4 Bo = sb[(ks * 8 + n16a + 1) * 32 + lane];
        uint4 A0 = aL[(mb0 * 2 + (ks - 6)) * 32 + lane];
        uint4 A1 = aL[((mb0 + 1) * 2 + (ks - 6)) * 32 + lane];
        mma16816(C[0][0], A0, Be.x, Be.y);
        mma16816(C[0][1], A0, Be.z, Be.w);
        mma16816(C[0][2], A0, Bo.x, Bo.y);
        mma16816(C[0][3], A0, Bo.z, Bo.w);
        mma16816(C[1][0], A1, Be.x, Be.y);
        mma16816(C[1][1], A1, Be.z, Be.w);
        mma16816(C[1][2], A1, Bo.x, Bo.y);
        mma16816(C[1][3], A1, Bo.z, Bo.w);
    }
}

// ---------------------------------------------------------------------------
__global__ void __launch_bounds__(NT, 1)
mlp_hmma_kernel(const float* __restrict__ hole, const float* __restrict__ board,
                const float* __restrict__ b1g, const float* __restrict__ b2g,
                float* __restrict__ out, int Btot)
{
    extern __shared__ __align__(16) unsigned char smp[];
    const int tid = threadIdx.x;
    const int w = tid >> 5, lane = tid & 31;
    const int g = lane >> 2, tg = lane & 3;
    const int row0 = blockIdx.x * BM;

    const uint32_t sm_u = smem_u32(smp);
    uint4* A1h = (uint4*)(smp + A1H_B);
    uint4* A1l = (uint4*)(smp + A1L_B);
    uint4* A2h = (uint4*)(smp + A2H_B);
    const float* sb1 = (const float*)(smp + B1S_B);

    // ---- zero A1 regions, stage b1 to smem, prologue piece issues ---------
    {
        uint4 z = make_uint4(0, 0, 0, 0);
#pragma unroll 2
        for (int i = tid; i < 2560; i += NT) ((uint4*)smp)[i] = z;
    }
    if (tid < 256)
        ((float4*)(smp + B1S_B))[tid] = ((const float4*)b1g)[tid];
    const uint32_t bb_u = sm_u + BB_B;
    issue_piece(0, bb_u, tid);
    issue_piece(1, bb_u, tid);
    __syncthreads();   // A1 zero + b1 stage visible before use

    // ---- per-row features + card bits -> A1 fragments ---------------------
    if (tid < BM) {
        int r = tid, grow = row0 + r;
        if (grow < Btot) {
            const float* hp = hole + (size_t)grow * 52;
            const float* bp = board + (size_t)grow * 52;
            const __half one = __float2half_rn(1.0f);
            int bsc[4] = {0, 0, 0, 0}, asc[4] = {0, 0, 0, 0};
            int bcount = 0, hcount = 0, pairs_b = 0, pairs_a = 0;
            bool trips_b = false, trips_a = false;
            int pb[17], pa[17];
#pragma unroll
            for (int rk = 0; rk < 13; rk++) {
                int b4 = 0, a4 = 0;
#pragma unroll
                for (int su = 0; su < 4; su++) {
                    int c = rk * 4 + su;
                    int hv = (hp[c] != 0.0f);
                    int bv = (bp[c] != 0.0f);
                    if (hv) *(__half*)(smp + A1H_B + afrag_off(r, c)) = one;
                    if (bv) *(__half*)(smp + A1H_B + afrag_off(r, 52 + c)) = one;
                    b4 += bv; a4 += hv + bv;
                    bcount += bv; hcount += hv;
                    bsc[su] += bv; asc[su] += hv + bv;
                }
                pairs_b += (b4 >= 2); trips_b |= (b4 >= 3);
                pairs_a += (a4 >= 2); trips_a |= (a4 >= 3);
                pb[rk] = (b4 > 0); pa[rk] = (a4 > 0);
            }
#pragma unroll
            for (int i = 13; i < 17; i++) { pb[i] = 0; pa[i] = 0; }

            float strength = trips_b ? 0.8f
                           : (pairs_b >= 2 ? 0.6f : (pairs_b >= 1 ? 0.4f : 0.2f));
            if (bcount == 0) strength = 0.0f;
            int maxbsc = max(max(bsc[0], bsc[1]), max(bsc[2], bsc[3]));
            float flush_b = (maxbsc >= 3 && bcount > 0) ? 1.0f : 0.0f;
            bool sb = false;
#pragma unroll
            for (int j = 0; j < 13; j++) {
                int ww = pb[j] + pb[j + 1] + pb[j + 2] + pb[j + 3] + pb[j + 4];
                if (ww >= 3) sb = true;
            }
            float straight_b = (sb && bcount > 0) ? 1.0f : 0.0f;
            float valid = (hcount >= 2 && bcount >= 1) ? 1.0f : 0.0f;
            int msc = max(max(asc[0], asc[1]), max(asc[2], asc[3]));
            float flush_draw = (msc == 4) ? 1.0f : 0.0f;
            float flush_outs = fmaxf(0.0f, 13.0f - (float)msc) / 13.0f;
            bool found = false; int c4_at = 0;
#pragma unroll
            for (int j = 0; j < 13; j++) {
                int c5 = pa[j] + pa[j + 1] + pa[j + 2] + pa[j + 3] + pa[j + 4];
                bool q = (pa[j] > 0) && (c5 >= 4);
                if (q && !found) {
                    found = true;
                    c4_at = pa[j] + pa[j + 1] + pa[j + 2] + pa[j + 3];
                }
            }
            float sd = found ? 1.0f : 0.0f;
            float so = found ? (c4_at >= 4 ? 0.4f : 0.2f) : 0.0f;
            float total_outs = flush_draw * flush_outs * 9.0f + sd * so * 8.0f;
            float remaining = 52.0f - (float)(hcount + bcount);
            float equity = (remaining > 0.0f)
                ? fminf(1.0f, total_outs / fmaxf(remaining, 1.0f)) : 0.0f;

            float feats[15];
            feats[0] = strength; feats[1] = flush_b; feats[2] = straight_b;
            feats[3] = (bcount == 0) ? 1.0f : 0.0f;
            feats[4] = (bcount == 3) ? 1.0f : 0.0f;
            feats[5] = (bcount == 4) ? 1.0f : 0.0f;
            feats[6] = (bcount == 5) ? 1.0f : 0.0f;
            feats[7]  = valid * flush_draw;
            feats[8]  = valid * flush_outs;
            feats[9]  = valid * sd;
            feats[10] = valid * so;
            feats[11] = valid * equity;
            feats[12] = valid * ((pairs_a >= 1) ? 1.0f : 0.0f);
            feats[13] = valid * (trips_a ? 1.0f : 0.0f);
            feats[14] = valid * ((pairs_a >= 2) ? 1.0f : 0.0f);
#pragma unroll
            for (int t = 0; t < 15; t++) {
                float f = feats[t];
                float fh = f16rt(f);
                int cl = 104 + t;
                *(__half*)(smp + A1H_B + afrag_off(r, cl)) = __float2half_rn(f);
                *(__half*)(smp + A1L_B + lofrag_off(r, cl)) =
                    __float2half_rn(f - fh);
            }
        }
    }

    const int mb0 = (w >> 2) * 2;   // warp M-range: rows mb0*16 .. +32
    const int nq  = (w & 3);        // warp N-range: n8 blocks nq*4 .. +4
    const int n16a = nq * 2;

    float C2[2][2][4][4];           // [half][mbi][j][reg]
#pragma unroll
    for (int h = 0; h < 2; h++)
#pragma unroll
        for (int mi = 0; mi < 2; mi++)
#pragma unroll
            for (int j = 0; j < 4; j++)
#pragma unroll
                for (int q = 0; q < 4; q++) C2[h][mi][j][q] = 0.0f;

    int p = 0;
    for (int c = 0; c < 8; c++) {
        float C1[2][4][4];
#pragma unroll
        for (int mi = 0; mi < 2; mi++)
#pragma unroll
            for (int j = 0; j < 4; j++)
#pragma unroll
                for (int q = 0; q < 4; q++) C1[mi][j][q] = 0.0f;

        // stage A: piece 3c (W1) — wait; ONE sync; issue p+2; compute
        CP_WAIT1(); __syncthreads();
        issue_piece(p + 2, bb_u, tid);
        {
            const uint4* sbp = (const uint4*)(smp + BB_B + piece_slot(p));
            gemm_term(C1, A1h, sbp, mb0, n16a, lane);
            gemm_term_lo1(C1, A1l, sbp, mb0, n16a, lane);
        }
        p++;

        // epilogue: add b1 (from smem, mi-invariant loads hoisted), relu,
        // fp16 round, store as A2 fragments
#pragma unroll
        for (int jp = 0; jp < 2; jp++) {
            int ksg = nq * 2 + jp;
            int n0e = (nq * 4 + 2 * jp) * 8 + tg * 2;
            float2 b1e = *(const float2*)(sb1 + c * 128 + n0e);
            float2 b1o = *(const float2*)(sb1 + c * 128 + n0e + 8);
#pragma unroll
            for (int mi = 0; mi < 2; mi++) {
                float* fe = C1[mi][2 * jp];
                float* fo = C1[mi][2 * jp + 1];
                float e0 = fmaxf(fe[0] + b1e.x, 0.0f);
                float e1 = fmaxf(fe[1] + b1e.y, 0.0f);
                float e2 = fmaxf(fe[2] + b1e.x, 0.0f);
                float e3 = fmaxf(fe[3] + b1e.y, 0.0f);
                float o0 = fmaxf(fo[0] + b1o.x, 0.0f);
                float o1 = fmaxf(fo[1] + b1o.y, 0.0f);
                float o2 = fmaxf(fo[2] + b1o.x, 0.0f);
                float o3 = fmaxf(fo[3] + b1o.y, 0.0f);
                uint4 hv;
                hv.x = pack_f16(e0, e1); hv.y = pack_f16(e2, e3);
                hv.z = pack_f16(o0, o1); hv.w = pack_f16(o2, o3);
                int idx = ((mb0 + mi) * 8 + ksg) * 32 + lane;
                A2h[idx] = hv;
            }
        }

        // stage B: piece 3c+1 (W2 half0)
        CP_WAIT1(); __syncthreads();
        issue_piece(p + 2, bb_u, tid);
        gemm_term(C2[0], A2h,
                  (const uint4*)(smp + BB_B + piece_slot(p)), mb0, n16a, lane);
        p++;

        // stage C: piece 3c+2 (W2 half1)
        CP_WAIT1(); __syncthreads();
        issue_piece(p + 2, bb_u, tid);
        gemm_term(C2[1], A2h,
                  (const uint4*)(smp + BB_B + piece_slot(p)), mb0, n16a, lane);
        p++;
    }

    // ---- final epilogue: C2 + b2 -> out -----------------------------------
#pragma unroll
    for (int h = 0; h < 2; h++) {
#pragma unroll
        for (int mi = 0; mi < 2; mi++) {
            int r0 = row0 + (mb0 + mi) * 16 + g;
#pragma unroll
            for (int j = 0; j < 4; j++) {
                int n0 = h * 128 + (nq * 4 + j) * 8 + tg * 2;
                float2 bb = *(const float2*)(b2g + n0);
                float* cc = C2[h][mi][j];
                if (r0 < Btot) {
                    float2 v = make_float2(cc[0] + bb.x, cc[1] + bb.y);
                    *(float2*)(out + (size_t)r0 * OUTDIM + n0) = v;
                }
                if (r0 + 8 < Btot) {
                    float2 v = make_float2(cc[2] + bb.x, cc[3] + bb.y);
                    *(float2*)(out + (size_t)(r0 + 8) * OUTDIM + n0) = v;
                }
            }
        }
    }
}

// ---------------------------------------------------------------------------
extern "C" void kernel_launch(void* const* d_in, const int* in_sizes, int n_in,
                              void* d_out, int out_size)
{
    const float* hole  = (const float*)d_in[0];
    const float* board = (const float*)d_in[1];
    const float* W1    = (const float*)d_in[2];
    const float* b1    = (const float*)d_in[3];
    const float* W2    = (const float*)d_in[4];
    const float* b2    = (const float*)d_in[5];
    float* out = (float*)d_out;

    int B = in_sizes[0] / 52;
    int blocks = (B + BM - 1) / BM;

    prep_w1<<<(8 * 8192 + 255) / 256, 256>>>(W1);
    prep_w2<<<(16 * 8192 + 255) / 256, 256>>>(W2);

    cudaFuncSetAttribute(mlp_hmma_kernel,
                         cudaFuncAttributeMaxDynamicSharedMemorySize, SMEMB);
    mlp_hmma_kernel<<<blocks, NT, SMEMB>>>(hole, board, b1, b2, out, B);
}

// round 17
// speedup vs baseline: 1.1224x; 1.0207x over previous
#include <cuda_runtime.h>
#include <cuda_fp16.h>
#include <cstdint>

// ===========================================================================
// Fused poker-feature MLP via mma.sync (HMMA fp16).
//   out[B,256] = relu(x @ W1 + b1) @ W2 + b2,  x = [hole|board|feats] (119)
//
// R16 = R15 (354.3us) + two more critical-path load conversions (the only
//       change family that has consistently won):
//   - feature phase reads hole/board as float4 (26 LDG.128 vs 104 LDG.32
//     per row-thread; these 4 warps gate stage A's first barrier)
//   - b2 (1KB) staged to smem in the prologue (tail epilogue LDG -> LDS)
// Math identical to R12/R15.  rel_err must equal 3.682313e-4 exactly.
// ===========================================================================

#define NT     512
#define BM     128
#define IND    119
#define HID    1024
#define OUTDIM 256

// smem byte offsets
#define A1H_B 0u        // [mb8][ks8][lane32][16B] = 32KB
#define A1L_B 32768u    // [mb8][ks2][lane32][16B] = 8KB (k 96..127 only)
#define A2H_B 40960u    // [mb8][ks8][lane32][16B] = 32KB
#define BB_B  73728u    // 3 x 32KB piece slots
#define B1S_B 172032u   // staged b1: 1024 floats = 4KB
#define B2S_B 176128u   // staged b2: 256 floats = 1KB
#define SMEMB 177152u

#define NPIECES 24      // 8 chunks x 3 pieces (W1, W2h0, W2h1)

// fragment-ordered weight images (fp16 hi only)
__device__ __align__(16) unsigned char gW1frag[8 * 32768];   // [c]
__device__ __align__(16) unsigned char gW2frag[16 * 32768];  // [c][half]

// ---------------------------------------------------------------------------
__device__ __forceinline__ unsigned pack_f16(float a, float b) {
    __half2 t = __floats2half2_rn(a, b);
    return *(unsigned*)&t;
}
__device__ __forceinline__ float f16rt(float a) {
    return __half2float(__float2half_rn(a));
}
__device__ __forceinline__ uint32_t smem_u32(const void* p) {
    uint32_t a;
    asm("{ .reg .u64 t; cvta.to.shared.u64 t, %1; cvt.u32.u64 %0, t; }"
        : "=r"(a) : "l"(p));
    return a;
}
__device__ __forceinline__ void mma16816(float c[4], const uint4& A,
                                         unsigned b0, unsigned b1) {
    asm volatile(
        "mma.sync.aligned.m16n8k16.row.col.f32.f16.f16.f32 "
        "{%0,%1,%2,%3}, {%4,%5,%6,%7}, {%8,%9}, {%0,%1,%2,%3};\n"
        : "+f"(c[0]), "+f"(c[1]), "+f"(c[2]), "+f"(c[3])
        : "r"(A.x), "r"(A.y), "r"(A.z), "r"(A.w), "r"(b0), "r"(b1));
}
#define CP_WAIT1() asm volatile("cp.async.wait_group 1;" ::: "memory")

// byte offset of element (row r, col cl) in an A-fragment region (8 mblks)
__device__ __forceinline__ uint32_t afrag_off(int r, int cl) {
    int mb = r >> 4, i = r & 15, ks = cl >> 4, jj = cl & 15;
    int lane = ((i & 7) << 2) + ((jj & 7) >> 1);
    int reg = (i >> 3) + ((jj >> 3) << 1);
    return ((((mb << 3) + ks) << 5) + lane) * 16u + (reg << 2) + ((jj & 1) << 1);
}
// 2-kstep lo region (k 96..127)
__device__ __forceinline__ uint32_t lofrag_off(int r, int cl) {
    int mb = r >> 4, i = r & 15, ks = (cl >> 4) - 6, jj = cl & 15;
    int lane = ((i & 7) << 2) + ((jj & 7) >> 1);
    int reg = (i >> 3) + ((jj >> 3) << 1);
    return ((((mb << 1) + ks) << 5) + lane) * 16u + (reg << 2) + ((jj & 1) << 1);
}

// ---------------------------------------------------------------------------
// Prep: cook fp16 fragment images (layout identical to R9/R12).
// ---------------------------------------------------------------------------
__global__ void prep_w1(const float* __restrict__ W1) {
    int id = blockIdx.x * blockDim.x + threadIdx.x;
    if (id >= 8 * 8192) return;
    int c = id >> 13, q = id & 8191;
    int ks = q >> 10, n16 = (q >> 7) & 7, lane = (q >> 2) & 31, j = q & 3;
    int n8 = n16 * 2 + (j >> 1), breg = j & 1;
    int k = ks * 16 + (lane & 3) * 2 + breg * 8;
    int n = n8 * 8 + (lane >> 2);
    float v0 = (k < IND)     ? W1[k * HID + c * 128 + n]       : 0.0f;
    float v1 = (k + 1 < IND) ? W1[(k + 1) * HID + c * 128 + n] : 0.0f;
    ((unsigned*)gW1frag)[c * 8192 + q] = pack_f16(v0, v1);
}
__global__ void prep_w2(const float* __restrict__ W2) {
    int id = blockIdx.x * blockDim.x + threadIdx.x;
    if (id >= 16 * 8192) return;
    int pi = id >> 13, q = id & 8191;
    int c = pi >> 1, half = pi & 1;
    int ks = q >> 10, n16 = (q >> 7) & 7, lane = (q >> 2) & 31, j = q & 3;
    int n8 = n16 * 2 + (j >> 1), breg = j & 1;
    int k = ks * 16 + (lane & 3) * 2 + breg * 8;
    int n = n8 * 8 + (lane >> 2);
    float v0 = W2[(c * 128 + k) * OUTDIM + half * 128 + n];
    float v1 = W2[(c * 128 + k + 1) * OUTDIM + half * 128 + n];
    ((unsigned*)gW2frag)[pi * 8192 + q] = pack_f16(v0, v1);
}

// ---------------------------------------------------------------------------
__device__ __forceinline__ const unsigned char* piece_src(int p) {
    int c = p / 3, t = p % 3;
    if (t == 0) return gW1frag + (size_t)c * 32768u;
    return gW2frag + (size_t)((c << 1) + (t - 1)) * 32768u;
}
// slot for piece p in the 3-slot ring
__device__ __forceinline__ uint32_t piece_slot(int p) {
    return (uint32_t)(p % 3) * 32768u;
}
__device__ __forceinline__ void issue_piece(int p, uint32_t bb_u32, int tid) {
    if (p < NPIECES) {
        const unsigned char* src = piece_src(p) + tid * 64;
        uint32_t dst = bb_u32 + piece_slot(p) + (uint32_t)tid * 64u;
#pragma unroll
        for (int i = 0; i < 4; i++)
            asm volatile("cp.async.cg.shared.global [%0], [%1], 16;"
                         :: "r"(dst + i * 16), "l"(src + i * 16));
    }
    asm volatile("cp.async.commit_group;" ::: "memory");
}

// full-K single-A term: C[2][4][4] += A * B
__device__ __forceinline__ void gemm_term(float C[2][4][4],
                                          const uint4* __restrict__ aF,
                                          const uint4* __restrict__ sb,
                                          int mb0, int n16a, int lane) {
#pragma unroll
    for (int ks = 0; ks < 8; ks++) {
        uint4 Be = sb[(ks * 8 + n16a) * 32 + lane];
        uint4 Bo = sb[(ks * 8 + n16a + 1) * 32 + lane];
        uint4 A0 = aF[(mb0 * 8 + ks) * 32 + lane];
        uint4 A1 = aF[((mb0 + 1) * 8 + ks) * 32 + lane];
        mma16816(C[0][0], A0, Be.x, Be.y);
        mma16816(C[0][1], A0, Be.z, Be.w);
        mma16816(C[0][2], A0, Bo.x, Bo.y);
        mma16816(C[0][3], A0, Bo.z, Bo.w);
        mma16816(C[1][0], A1, Be.x, Be.y);
        mma16816(C[1][1], A1, Be.z, Be.w);
        mma16816(C[1][2], A1, Bo.x, Bo.y);
        mma16816(C[1][3], A1, Bo.z, Bo.w);
    }
}
// GEMM1 x-lo term: only ksteps 6,7 live in the 2-kstep lo region
__device__ __forceinline__ void gemm_term_lo1(float C[2][4][4],
                                              const uint4* __restrict__ aL,
                                              const uint4* __restrict__ sb,
                                              int mb0, int n16a, int lane) {
#pragma unroll
    for (int ks = 6; ks < 8; ks++) {
        uint4 Be = sb[(ks * 8 + n16a) * 32 + lane];
        uint4 Bo = sb[(ks * 8 + n16a + 1) * 32 + lane];
        uint4 A0 = aL[(mb0 * 2 + (ks - 6)) * 32 + lane];
        uint4 A1 = aL[((mb0 + 1) * 2 + (ks - 6)) * 32 + lane];
        mma16816(C[0][0], A0, Be.x, Be.y);
        mma16816(C[0][1], A0, Be.z, Be.w);
        mma16816(C[0][2], A0, Bo.x, Bo.y);
        mma16816(C[0][3], A0, Bo.z, Bo.w);
        mma16816(C[1][0], A1, Be.x, Be.y);
        mma16816(C[1][1], A1, Be.z, Be.w);
        mma16816(C[1][2], A1, Bo.x, Bo.y);
        mma16816(C[1][3], A1, Bo.z, Bo.w);
    }
}

// ---------------------------------------------------------------------------
__global__ void __launch_bounds__(NT, 1)
mlp_hmma_kernel(const float* __restrict__ hole, const float* __restrict__ board,
                const float* __restrict__ b1g, const float* __restrict__ b2g,
                float* __restrict__ out, int Btot)
{
    extern __shared__ __align__(16) unsigned char smp[];
    const int tid = threadIdx.x;
    const int w = tid >> 5, lane = tid & 31;
    const int g = lane >> 2, tg = lane & 3;
    const int row0 = blockIdx.x * BM;

    const uint32_t sm_u = smem_u32(smp);
    uint4* A1h = (uint4*)(smp + A1H_B);
    uint4* A1l = (uint4*)(smp + A1L_B);
    uint4* A2h = (uint4*)(smp + A2H_B);
    const float* sb1 = (const float*)(smp + B1S_B);
    const float* sb2 = (const float*)(smp + B2S_B);

    // ---- zero A1 regions, stage b1+b2 to smem, prologue piece issues ------
    {
        uint4 z = make_uint4(0, 0, 0, 0);
#pragma unroll 2
        for (int i = tid; i < 2560; i += NT) ((uint4*)smp)[i] = z;
    }
    if (tid < 256)
        ((float4*)(smp + B1S_B))[tid] = ((const float4*)b1g)[tid];
    else if (tid < 320)
        ((float4*)(smp + B2S_B))[tid - 256] = ((const float4*)b2g)[tid - 256];
    const uint32_t bb_u = sm_u + BB_B;
    issue_piece(0, bb_u, tid);
    issue_piece(1, bb_u, tid);
    __syncthreads();   // A1 zero + bias stages visible before use

    // ---- per-row features + card bits -> A1 fragments ---------------------
    if (tid < BM) {
        int r = tid, grow = row0 + r;
        if (grow < Btot) {
            const float4* hp4 = (const float4*)(hole + (size_t)grow * 52);
            const float4* bp4 = (const float4*)(board + (size_t)grow * 52);
            const __half one = __float2half_rn(1.0f);
            int bsc[4] = {0, 0, 0, 0}, asc[4] = {0, 0, 0, 0};
            int bcount = 0, hcount = 0, pairs_b = 0, pairs_a = 0;
            bool trips_b = false, trips_a = false;
            int pb[17], pa[17];
#pragma unroll
            for (int rk = 0; rk < 13; rk++) {
                float4 hq = hp4[rk];
                float4 bq = bp4[rk];
                float hvv[4] = {hq.x, hq.y, hq.z, hq.w};
                float bvv[4] = {bq.x, bq.y, bq.z, bq.w};
                int b4 = 0, a4 = 0;
#pragma unroll
                for (int su = 0; su < 4; su++) {
                    int c = rk * 4 + su;
                    int hv = (hvv[su] != 0.0f);
                    int bv = (bvv[su] != 0.0f);
                    if (hv) *(__half*)(smp + A1H_B + afrag_off(r, c)) = one;
                    if (bv) *(__half*)(smp + A1H_B + afrag_off(r, 52 + c)) = one;
                    b4 += bv; a4 += hv + bv;
                    bcount += bv; hcount += hv;
                    bsc[su] += bv; asc[su] += hv + bv;
                }
                pairs_b += (b4 >= 2); trips_b |= (b4 >= 3);
                pairs_a += (a4 >= 2); trips_a |= (a4 >= 3);
                pb[rk] = (b4 > 0); pa[rk] = (a4 > 0);
            }
#pragma unroll
            for (int i = 13; i < 17; i++) { pb[i] = 0; pa[i] = 0; }

            float strength = trips_b ? 0.8f
                           : (pairs_b >= 2 ? 0.6f : (pairs_b >= 1 ? 0.4f : 0.2f));
            if (bcount == 0) strength = 0.0f;
            int maxbsc = max(max(bsc[0], bsc[1]), max(bsc[2], bsc[3]));
            float flush_b = (maxbsc >= 3 && bcount > 0) ? 1.0f : 0.0f;
            bool sb = false;
#pragma unroll
            for (int j = 0; j < 13; j++) {
                int ww = pb[j] + pb[j + 1] + pb[j + 2] + pb[j + 3] + pb[j + 4];
                if (ww >= 3) sb = true;
            }
            float straight_b = (sb && bcount > 0) ? 1.0f : 0.0f;
            float valid = (hcount >= 2 && bcount >= 1) ? 1.0f : 0.0f;
            int msc = max(max(asc[0], asc[1]), max(asc[2], asc[3]));
            float flush_draw = (msc == 4) ? 1.0f : 0.0f;
            float flush_outs = fmaxf(0.0f, 13.0f - (float)msc) / 13.0f;
            bool found = false; int c4_at = 0;
#pragma unroll
            for (int j = 0; j < 13; j++) {
                int c5 = pa[j] + pa[j + 1] + pa[j + 2] + pa[j + 3] + pa[j + 4];
                bool q = (pa[j] > 0) && (c5 >= 4);
                if (q && !found) {
                    found = true;
                    c4_at = pa[j] + pa[j + 1] + pa[j + 2] + pa[j + 3];
                }
            }
            float sd = found ? 1.0f : 0.0f;
            float so = found ? (c4_at >= 4 ? 0.4f : 0.2f) : 0.0f;
            float total_outs = flush_draw * flush_outs * 9.0f + sd * so * 8.0f;
            float remaining = 52.0f - (float)(hcount + bcount);
            float equity = (remaining > 0.0f)
                ? fminf(1.0f, total_outs / fmaxf(remaining, 1.0f)) : 0.0f;

            float feats[15];
            feats[0] = strength; feats[1] = flush_b; feats[2] = straight_b;
            feats[3] = (bcount == 0) ? 1.0f : 0.0f;
            feats[4] = (bcount == 3) ? 1.0f : 0.0f;
            feats[5] = (bcount == 4) ? 1.0f : 0.0f;
            feats[6] = (bcount == 5) ? 1.0f : 0.0f;
            feats[7]  = valid * flush_draw;
            feats[8]  = valid * flush_outs;
            feats[9]  = valid * sd;
            feats[10] = valid * so;
            feats[11] = valid * equity;
            feats[12] = valid * ((pairs_a >= 1) ? 1.0f : 0.0f);
            feats[13] = valid * (trips_a ? 1.0f : 0.0f);
            feats[14] = valid * ((pairs_a >= 2) ? 1.0f : 0.0f);
#pragma unroll
            for (int t = 0; t < 15; t++) {
                float f = feats[t];
                float fh = f16rt(f);
                int cl = 104 + t;
                *(__half*)(smp + A1H_B + afrag_off(r, cl)) = __float2half_rn(f);
                *(__half*)(smp + A1L_B + lofrag_off(r, cl)) =
                    __float2half_rn(f - fh);
            }
        }
    }

    const int mb0 = (w >> 2) * 2;   // warp M-range: rows mb0*16 .. +32
    const int nq  = (w & 3);        // warp N-range: n8 blocks nq*4 .. +4
    const int n16a = nq * 2;

    float C2[2][2][4][4];           // [half][mbi][j][reg]
#pragma unroll
    for (int h = 0; h < 2; h++)
#pragma unroll
        for (int mi = 0; mi < 2; mi++)
#pragma unroll
            for (int j = 0; j < 4; j++)
#pragma unroll
                for (int q = 0; q < 4; q++) C2[h][mi][j][q] = 0.0f;

    int p = 0;
    for (int c = 0; c < 8; c++) {
        float C1[2][4][4];
#pragma unroll
        for (int mi = 0; mi < 2; mi++)
#pragma unroll
            for (int j = 0; j < 4; j++)
#pragma unroll
                for (int q = 0; q < 4; q++) C1[mi][j][q] = 0.0f;

        // stage A: piece 3c (W1) — wait; ONE sync; issue p+2; compute
        CP_WAIT1(); __syncthreads();
        issue_piece(p + 2, bb_u, tid);
        {
            const uint4* sbp = (const uint4*)(smp + BB_B + piece_slot(p));
            gemm_term(C1, A1h, sbp, mb0, n16a, lane);
            gemm_term_lo1(C1, A1l, sbp, mb0, n16a, lane);
        }
        p++;

        // epilogue: add b1 (smem, hoisted), relu, fp16 round -> A2 fragments
#pragma unroll
        for (int jp = 0; jp < 2; jp++) {
            int ksg = nq * 2 + jp;
            int n0e = (nq * 4 + 2 * jp) * 8 + tg * 2;
            float2 b1e = *(const float2*)(sb1 + c * 128 + n0e);
            float2 b1o = *(const float2*)(sb1 + c * 128 + n0e + 8);
#pragma unroll
            for (int mi = 0; mi < 2; mi++) {
                float* fe = C1[mi][2 * jp];
                float* fo = C1[mi][2 * jp + 1];
                float e0 = fmaxf(fe[0] + b1e.x, 0.0f);
                float e1 = fmaxf(fe[1] + b1e.y, 0.0f);
                float e2 = fmaxf(fe[2] + b1e.x, 0.0f);
                float e3 = fmaxf(fe[3] + b1e.y, 0.0f);
                float o0 = fmaxf(fo[0] + b1o.x, 0.0f);
                float o1 = fmaxf(fo[1] + b1o.y, 0.0f);
                float o2 = fmaxf(fo[2] + b1o.x, 0.0f);
                float o3 = fmaxf(fo[3] + b1o.y, 0.0f);
                uint4 hv;
                hv.x = pack_f16(e0, e1); hv.y = pack_f16(e2, e3);
                hv.z = pack_f16(o0, o1); hv.w = pack_f16(o2, o3);
                int idx = ((mb0 + mi) * 8 + ksg) * 32 + lane;
                A2h[idx] = hv;
            }
        }

        // stage B: piece 3c+1 (W2 half0)
        CP_WAIT1(); __syncthreads();
        issue_piece(p + 2, bb_u, tid);
        gemm_term(C2[0], A2h,
                  (const uint4*)(smp + BB_B + piece_slot(p)), mb0, n16a, lane);
        p++;

        // stage C: piece 3c+2 (W2 half1)
        CP_WAIT1(); __syncthreads();
        issue_piece(p + 2, bb_u, tid);
        gemm_term(C2[1], A2h,
                  (const uint4*)(smp + BB_B + piece_slot(p)), mb0, n16a, lane);
        p++;
    }

    // ---- final epilogue: C2 + b2 (smem) -> out ----------------------------
#pragma unroll
    for (int h = 0; h < 2; h++) {
#pragma unroll
        for (int mi = 0; mi < 2; mi++) {
            int r0 = row0 + (mb0 + mi) * 16 + g;
#pragma unroll
            for (int j = 0; j < 4; j++) {
                int n0 = h * 128 + (nq * 4 + j) * 8 + tg * 2;
                float2 bb = *(const float2*)(sb2 + n0);
                float* cc = C2[h][mi][j];
                if (r0 < Btot) {
                    float2 v = make_float2(cc[0] + bb.x, cc[1] + bb.y);
                    *(float2*)(out + (size_t)r0 * OUTDIM + n0) = v;
                }
                if (r0 + 8 < Btot) {
                    float2 v = make_float2(cc[2] + bb.x, cc[3] + bb.y);
                    *(float2*)(out + (size_t)(r0 + 8) * OUTDIM + n0) = v;
                }
            }
        }
    }
}

// ---------------------------------------------------------------------------
extern "C" void kernel_launch(void* const* d_in, const int* in_sizes, int n_in,
                              void* d_out, int out_size)
{
    const float* hole  = (const float*)d_in[0];
    const float* board = (const float*)d_in[1];
    const float* W1    = (const float*)d_in[2];
    const float* b1    = (const float*)d_in[3];
    const float* W2    = (const float*)d_in[4];
    const float* b2    = (const float*)d_in[5];
    float* out = (float*)d_out;

    int B = in_sizes[0] / 52;
    int blocks = (B + BM - 1) / BM;

    prep_w1<<<(8 * 8192 + 255) / 256, 256>>>(W1);
    prep_w2<<<(16 * 8192 + 255) / 256, 256>>>(W2);

    cudaFuncSetAttribute(mlp_hmma_kernel,
                         cudaFuncAttributeMaxDynamicSharedMemorySize, SMEMB);
    mlp_hmma_kernel<<<blocks, NT, SMEMB>>>(hole, board, b1, b2, out, B);
}